// round 16
// baseline (speedup 1.0000x reference)
#include <cuda_runtime.h>
#include <math.h>

#define B_ 8
#define H_ 96
#define W_ 96
#define O_ 8
#define NACC 60          // 6 C-pairs x 10 Q-pairs
#define CPB 37           // CTAs per b  -> grid 8*37 = 296 = 2*148 (one wave)
#define CHUNKS 288       // 256-point chunks per b
#define PPB (H_*W_*O_)   // 73728 points per b

__device__ float        g_sum[B_][O_][NACC];
__device__ unsigned int g_ticket[B_];

#define CP_ASYNC16(dst_smem_u32, src_gmem_ptr) \
    asm volatile("cp.async.cg.shared.global [%0], [%1], 16;\n" \
                 :: "r"(dst_smem_u32), "l"(src_gmem_ptr))
#define CP_COMMIT()  asm volatile("cp.async.commit_group;\n" ::: "memory")
#define CP_WAIT1()   asm volatile("cp.async.wait_group 1;\n" ::: "memory")
#define CP_WAIT0()   asm volatile("cp.async.wait_group 0;\n" ::: "memory")

__global__ __launch_bounds__(256, 2)
void mtm_onepass_kernel(const void* __restrict__ objv,
                        const void* __restrict__ wpixv,
                        const void* __restrict__ camv,
                        const void* __restrict__ coordKv,
                        float* __restrict__ out)
{
    __shared__ int    s_is64;
    __shared__ int    s_last;
    __shared__ float4 s_wpix[2][256];      // 8 KB
    __shared__ float  s_obj[2][768];       // 6 KB
    __shared__ float  red[8 * 8 * NACC];   // 15 KB
    __shared__ float  s_sum[O_][NACC];

    const int b   = blockIdx.x / CPB;
    const int cta = blockIdx.x - b * CPB;
    const int tid = threadIdx.x;
    const int o   = tid & 7;

    // inline dtype probe (f32 vs f64), 256 parallel tests of the big buffer
    if (tid == 0) s_is64 = 0;
    __syncthreads();
    {
        float x = ((const float*)wpixv)[tid];
        if (!(fabsf(x) < 1.0e4f)) atomicOr(&s_is64, 1);
    }
    __syncthreads();
    const int is64 = s_is64;

    float acc[NACC];
#pragma unroll
    for (int i = 0; i < NACC; i++) acc[i] = 0.0f;

    if (is64 == 0) {
        const float* cam    = (const float*)camv;
        const float* coordK = (const float*)coordKv;
        const float* obj    = (const float*)objv;
        const float* wpix   = (const float*)wpixv;

        const float a   = -cam[b * 9 + 0];
        const float cb  = -cam[b * 9 + 4];
        const float du0 =  coordK[b * 4 + 2] - cam[b * 9 + 2];
        const float dv0 =  coordK[b * 4 + 3] - cam[b * 9 + 5];
        const float K00 =  coordK[b * 4 + 0];
        const float K01 =  coordK[b * 4 + 1];

        const unsigned w_base = (unsigned)__cvta_generic_to_shared(&s_wpix[0][0]);
        const unsigned o_base = (unsigned)__cvta_generic_to_shared(&s_obj[0][0]);

        // ---- async-load chunk k into buffer bf ----
        //   wpix: 256 x 16B (all threads); obj: 192 x 16B (threads < 192)
        // prologue: first chunk
        {
            const int k0 = cta;
            const float4* gw = (const float4*)wpix + (b * PPB + (k0 << 8));
            CP_ASYNC16(w_base + tid * 16, gw + tid);
            if (tid < 192) {
                const float4* go = (const float4*)(obj + (long)(b * PPB + (k0 << 8)) * 3);
                CP_ASYNC16(o_base + tid * 16, go + tid);
            }
            CP_COMMIT();
        }

        int buf = 0;
        for (int k = cta; k < CHUNKS; k += CPB) {
            const int kn = k + CPB;
            if (kn < CHUNKS) {                    // prefetch next chunk
                const int nb = buf ^ 1;
                const float4* gw = (const float4*)wpix + (b * PPB + (kn << 8));
                CP_ASYNC16(w_base + (nb * 4096) + tid * 16, gw + tid);
                if (tid < 192) {
                    const float4* go = (const float4*)(obj + (long)(b * PPB + (kn << 8)) * 3);
                    CP_ASYNC16(o_base + (nb * 3072) + tid * 16, go + tid);
                }
            }
            CP_COMMIT();                          // one group per iteration
            CP_WAIT1();                           // chunk k resident
            __syncthreads();

            // compute point (k*256 + tid) from smem
            const int pt = (k << 8) + tid;
            const int hw = pt >> 3;
            const int h  = hw / W_;
            const int w  = hw - h * W_;
            const float du = (float)w * K00 + du0;
            const float dv = (float)h * K01 + dv0;

            const float4 wv = s_wpix[buf][tid];
            const float p1 = s_obj[buf][tid * 3 + 0];
            const float p2 = s_obj[buf][tid * 3 + 1];
            const float p3 = s_obj[buf][tid * 3 + 2];

            const float cA0 = wv.x * a;
            const float cB0 = wv.y * cb;
            const float cC0 = wv.x * du + wv.y * dv;
            const float cA1 = wv.z * a;
            const float cB1 = wv.w * cb;
            const float cC1 = wv.z * du + wv.w * dv;

            float C[6];
            C[0] = cA0 * cA0 + cA1 * cA1;
            C[1] = cA0 * cB0 + cA1 * cB1;
            C[2] = cA0 * cC0 + cA1 * cC1;
            C[3] = cB0 * cB0 + cB1 * cB1;
            C[4] = cB0 * cC0 + cB1 * cC1;
            C[5] = cC0 * cC0 + cC1 * cC1;

            float q[9];
            q[0] = p1 * p1; q[1] = p1 * p2; q[2] = p1 * p3;
            q[3] = p2 * p2; q[4] = p2 * p3; q[5] = p3 * p3;
            q[6] = p1;      q[7] = p2;      q[8] = p3;

#pragma unroll
            for (int ci = 0; ci < 6; ci++) {
#pragma unroll
                for (int qi = 0; qi < 9; qi++)
                    acc[ci * 10 + qi] += C[ci] * q[qi];
                acc[ci * 10 + 9] += C[ci];
            }

            __syncthreads();                      // before buffer reuse
            buf ^= 1;
        }
        CP_WAIT0();
    } else {
        // f64 fallback: simple direct-global path (correctness only)
        const double* cam    = (const double*)camv;
        const double* coordK = (const double*)coordKv;
        const double* obj    = (const double*)objv;
        const double* wpix   = (const double*)wpixv;

        const float a   = -(float)cam[b * 9 + 0];
        const float cb  = -(float)cam[b * 9 + 4];
        const float du0 =  (float)(coordK[b * 4 + 2] - cam[b * 9 + 2]);
        const float dv0 =  (float)(coordK[b * 4 + 3] - cam[b * 9 + 5]);
        const float K00 =  (float)coordK[b * 4 + 0];
        const float K01 =  (float)coordK[b * 4 + 1];

#pragma unroll 1
        for (int k = cta; k < CHUNKS; k += CPB) {
            const int pt = (k << 8) + tid;
            const int hw = pt >> 3;
            const int h  = hw / W_;
            const int w  = hw - h * W_;
            const float du = (float)w * K00 + du0;
            const float dv = (float)h * K01 + dv0;

            const long idx = (long)b * PPB + pt;
            const double* op = obj  + idx * 3;
            const double* wp = wpix + idx * 4;
            const float p1 = (float)op[0], p2 = (float)op[1], p3 = (float)op[2];
            const float w0 = (float)wp[0], w1 = (float)wp[1];
            const float w2 = (float)wp[2], w3 = (float)wp[3];

            const float cA0 = w0 * a;
            const float cB0 = w1 * cb;
            const float cC0 = w0 * du + w1 * dv;
            const float cA1 = w2 * a;
            const float cB1 = w3 * cb;
            const float cC1 = w2 * du + w3 * dv;

            float C[6];
            C[0] = cA0 * cA0 + cA1 * cA1;
            C[1] = cA0 * cB0 + cA1 * cB1;
            C[2] = cA0 * cC0 + cA1 * cC1;
            C[3] = cB0 * cB0 + cB1 * cB1;
            C[4] = cB0 * cC0 + cB1 * cC1;
            C[5] = cC0 * cC0 + cC1 * cC1;

            float q[9];
            q[0] = p1 * p1; q[1] = p1 * p2; q[2] = p1 * p3;
            q[3] = p2 * p2; q[4] = p2 * p3; q[5] = p3 * p3;
            q[6] = p1;      q[7] = p2;      q[8] = p3;

#pragma unroll
            for (int ci = 0; ci < 6; ci++) {
#pragma unroll
                for (int qi = 0; qi < 9; qi++)
                    acc[ci * 10 + qi] += C[ci] * q[qi];
                acc[ci * 10 + 9] += C[ci];
            }
        }
    }

    // combine the 4 lanes in this warp sharing the same o (stride 8)
#pragma unroll
    for (int j = 0; j < NACC; j++) {
        float x = acc[j];
        x += __shfl_xor_sync(0xffffffffu, x, 8);
        x += __shfl_xor_sync(0xffffffffu, x, 16);
        acc[j] = x;
    }

    const int warp = tid >> 5;
    const int lane = tid & 31;
    if (lane < 8) {
#pragma unroll
        for (int j = 0; j < NACC; j++)
            red[(warp * 8 + lane) * NACC + j] = acc[j];
    }
    __syncthreads();

    // CTA totals -> compact global atomic accumulation (480 atomics/CTA)
    for (int task = tid; task < 8 * NACC; task += 256) {
        const int oo = task / NACC;
        const int j  = task - oo * NACC;
        double s = 0.0;
#pragma unroll
        for (int wp = 0; wp < 8; wp++)
            s += (double)red[(wp * 8 + oo) * NACC + j];
        atomicAdd(&g_sum[b][oo][j], (float)s);
    }

    // ---- last CTA of this b expands the 480 compact sums -> 1352 outputs ----
    __threadfence();
    if (tid == 0) {
        unsigned int t = atomicAdd(&g_ticket[b], 1u);
        s_last = (t == CPB - 1);
    }
    __syncthreads();
    if (!s_last) return;

    for (int kk = tid; kk < O_ * NACC; kk += 256) {
        const int oo = kk / NACC;
        const int j  = kk - oo * NACC;
        s_sum[oo][j] = __ldcg(&g_sum[b][oo][j]);
        g_sum[b][oo][j] = 0.0f;          // reset for next graph replay
    }
    __syncthreads();

    static const int imap[13] = {0,0,0, 1,1,1, 2,2,2, 0, 0,1,2};
    static const int kmap[13] = {0,1,2, 0,1,2, 0,1,2, 0, 3,3,3};
    static const int CIDX[3][3] = {{0,1,2},{1,3,4},{2,4,5}};
    static const int QIDX[4][4] = {{0,1,2,6},{1,3,4,7},{2,4,5,8},{6,7,8,9}};

    for (int task = tid; task < O_ * 169; task += 256) {
        const int oo = task / 169;
        const int t169 = task - oo * 169;
        const int al = t169 / 13;
        const int be = t169 - al * 13;
        float v = 0.0f;
        if (al != 9 && be != 9)
            v = s_sum[oo][CIDX[imap[al]][imap[be]] * 10 + QIDX[kmap[al]][kmap[be]]];
        out[(b * O_ + oo) * 169 + t169] = v;
    }

    if (tid == 0) g_ticket[b] = 0u;      // reset for next graph replay
}

extern "C" void kernel_launch(void* const* d_in, const int* in_sizes, int n_in,
                              void* d_out, int out_size)
{
    // Bind by size rank: w_pixel > obj > camera_matrix > coord_K.
    int order[8];
    int m = (n_in < 8) ? n_in : 8;
    for (int i = 0; i < m; i++) order[i] = i;
    for (int i = 0; i < m; i++)
        for (int j = i + 1; j < m; j++)
            if ((long long)in_sizes[order[j]] > (long long)in_sizes[order[i]]) {
                int t = order[i]; order[i] = order[j]; order[j] = t;
            }

    const void* wpix   = d_in[order[0]];
    const void* obj    = d_in[m > 1 ? order[1] : 0];
    const void* cam    = d_in[m > 2 ? order[2] : 0];
    const void* coordK = d_in[m > 3 ? order[3] : 0];
    float* out = (float*)d_out;

    mtm_onepass_kernel<<<B_ * CPB, 256>>>(obj, wpix, cam, coordK, out);
}

// round 17
// speedup vs baseline: 1.0579x; 1.0579x over previous
#include <cuda_runtime.h>
#include <math.h>

#define B_ 8
#define H_ 96
#define W_ 96
#define O_ 8
#define NACC 60          // 6 C-pairs x 10 Q-pairs (logical)
#define NACC2 30         // packed f32x2 accumulators
#define CPB 37           // CTAs per b -> grid 296 = 2*148 (one wave)
#define CHUNKS 288       // 256-point chunks per b
#define PPB (H_*W_*O_)   // 73728 points per b

__device__ float        g_sum[B_][O_][NACC];
__device__ unsigned int g_ticket[B_];

typedef unsigned long long u64x;
__device__ __forceinline__ u64x pk2(float lo, float hi) {
    u64x r; asm("mov.b64 %0,{%1,%2};" : "=l"(r) : "f"(lo), "f"(hi)); return r;
}
__device__ __forceinline__ void upk2(u64x v, float& lo, float& hi) {
    asm("mov.b64 {%0,%1},%2;" : "=f"(lo), "=f"(hi) : "l"(v));
}
__device__ __forceinline__ u64x fma2_(u64x a, u64x b, u64x c) {
    u64x d; asm("fma.rn.f32x2 %0,%1,%2,%3;" : "=l"(d) : "l"(a), "l"(b), "l"(c)); return d;
}
__device__ __forceinline__ u64x mul2_(u64x a, u64x b) {
    u64x d; asm("mul.rn.f32x2 %0,%1,%2;" : "=l"(d) : "l"(a), "l"(b)); return d;
}

__global__ __launch_bounds__(256, 2)
void mtm_onepass_kernel(const void* __restrict__ objv,
                        const void* __restrict__ wpixv,
                        const void* __restrict__ camv,
                        const void* __restrict__ coordKv,
                        float* __restrict__ out)
{
    __shared__ int s_is64;
    __shared__ int s_last;
    const int b   = blockIdx.x / CPB;
    const int cta = blockIdx.x - b * CPB;
    const int tid = threadIdx.x;

    // inline dtype probe (f32 vs f64), 256 parallel tests of the big buffer
    if (tid == 0) s_is64 = 0;
    __syncthreads();
    {
        float x = ((const float*)wpixv)[tid];
        if (!(fabsf(x) < 1.0e4f)) atomicOr(&s_is64, 1);
    }
    __syncthreads();
    const int is64 = s_is64;

    float acc[NACC];

    if (is64 == 0) {
        const float* cam    = (const float*)camv;
        const float* coordK = (const float*)coordKv;
        const float* obj    = (const float*)objv;
        const float* wpix   = (const float*)wpixv;

        const float a   = -cam[b * 9 + 0];
        const float cb  = -cam[b * 9 + 4];
        const float du0 =  coordK[b * 4 + 2] - cam[b * 9 + 2];
        const float dv0 =  coordK[b * 4 + 3] - cam[b * 9 + 5];
        const float K00 =  coordK[b * 4 + 0];
        const float K01 =  coordK[b * 4 + 1];

        u64x acc2[NACC2];
#pragma unroll
        for (int i = 0; i < NACC2; i++) acc2[i] = pk2(0.0f, 0.0f);

#pragma unroll 2
        for (int k = cta; k < CHUNKS; k += CPB) {
            const int pt = (k << 8) + tid;           // point within b
            const int hw = pt >> 3;
            const int h  = hw / W_;
            const int w  = hw - h * W_;
            const float du = (float)w * K00 + du0;
            const float dv = (float)h * K01 + dv0;

            const int idx = b * PPB + pt;
            const float4 wv = ((const float4*)wpix)[idx];
            const float* op = obj + idx * 3;
            const float p1 = op[0];
            const float p2 = op[1];
            const float p3 = op[2];

            const float cA0 = wv.x * a;
            const float cB0 = wv.y * cb;
            const float cC0 = wv.x * du + wv.y * dv;
            const float cA1 = wv.z * a;
            const float cB1 = wv.w * cb;
            const float cC1 = wv.z * du + wv.w * dv;

            const float C0 = cA0 * cA0 + cA1 * cA1;
            const float C1 = cA0 * cB0 + cA1 * cB1;
            const float C2 = cA0 * cC0 + cA1 * cC1;
            const float C3 = cB0 * cB0 + cB1 * cB1;
            const float C4 = cB0 * cC0 + cB1 * cC1;
            const float C5 = cC0 * cC0 + cC1 * cC1;

            u64x Cp[6];
            Cp[0] = pk2(C0, C0); Cp[1] = pk2(C1, C1); Cp[2] = pk2(C2, C2);
            Cp[3] = pk2(C3, C3); Cp[4] = pk2(C4, C4); Cp[5] = pk2(C5, C5);

            // q pairs: {p1²,p1p2} {p1p3,p2²} {p2p3,p3²} {p1,p2} {p3,1}
            const u64x pb = pk2(p1, p2);
            u64x qp[5];
            qp[0] = mul2_(pk2(p1, p1), pb);
            qp[1] = mul2_(pb, pk2(p3, p2));
            qp[2] = mul2_(pk2(p2, p3), pk2(p3, p3));
            qp[3] = pb;
            qp[4] = pk2(p3, 1.0f);

#pragma unroll
            for (int ci = 0; ci < 6; ci++) {
#pragma unroll
                for (int t = 0; t < 5; t++)
                    acc2[ci * 5 + t] = fma2_(Cp[ci], qp[t], acc2[ci * 5 + t]);
            }
        }

        // unpack packed accumulators into the logical acc[60] layout
#pragma unroll
        for (int i = 0; i < NACC2; i++) {
            const int ci = i / 5, t = i - ci * 5;
            upk2(acc2[i], acc[ci * 10 + 2 * t], acc[ci * 10 + 2 * t + 1]);
        }
    } else {
        // f64 fallback: simple direct-global path (correctness only)
#pragma unroll
        for (int i = 0; i < NACC; i++) acc[i] = 0.0f;

        const double* cam    = (const double*)camv;
        const double* coordK = (const double*)coordKv;
        const double* obj    = (const double*)objv;
        const double* wpix   = (const double*)wpixv;

        const float a   = -(float)cam[b * 9 + 0];
        const float cb  = -(float)cam[b * 9 + 4];
        const float du0 =  (float)(coordK[b * 4 + 2] - cam[b * 9 + 2]);
        const float dv0 =  (float)(coordK[b * 4 + 3] - cam[b * 9 + 5]);
        const float K00 =  (float)coordK[b * 4 + 0];
        const float K01 =  (float)coordK[b * 4 + 1];

#pragma unroll 1
        for (int k = cta; k < CHUNKS; k += CPB) {
            const int pt = (k << 8) + tid;
            const int hw = pt >> 3;
            const int h  = hw / W_;
            const int w  = hw - h * W_;
            const float du = (float)w * K00 + du0;
            const float dv = (float)h * K01 + dv0;

            const long idx = (long)b * PPB + pt;
            const double* op = obj  + idx * 3;
            const double* wp = wpix + idx * 4;
            const float p1 = (float)op[0], p2 = (float)op[1], p3 = (float)op[2];
            const float w0 = (float)wp[0], w1 = (float)wp[1];
            const float w2 = (float)wp[2], w3 = (float)wp[3];

            const float cA0 = w0 * a;
            const float cB0 = w1 * cb;
            const float cC0 = w0 * du + w1 * dv;
            const float cA1 = w2 * a;
            const float cB1 = w3 * cb;
            const float cC1 = w2 * du + w3 * dv;

            float C[6];
            C[0] = cA0 * cA0 + cA1 * cA1;
            C[1] = cA0 * cB0 + cA1 * cB1;
            C[2] = cA0 * cC0 + cA1 * cC1;
            C[3] = cB0 * cB0 + cB1 * cB1;
            C[4] = cB0 * cC0 + cB1 * cC1;
            C[5] = cC0 * cC0 + cC1 * cC1;

            float q[9];
            q[0] = p1 * p1; q[1] = p1 * p2; q[2] = p1 * p3;
            q[3] = p2 * p2; q[4] = p2 * p3; q[5] = p3 * p3;
            q[6] = p1;      q[7] = p2;      q[8] = p3;

#pragma unroll
            for (int ci = 0; ci < 6; ci++) {
#pragma unroll
                for (int qi = 0; qi < 9; qi++)
                    acc[ci * 10 + qi] += C[ci] * q[qi];
                acc[ci * 10 + 9] += C[ci];
            }
        }
    }

    // combine the 4 lanes in this warp sharing the same o (o = tid & 7)
#pragma unroll
    for (int j = 0; j < NACC; j++) {
        float x = acc[j];
        x += __shfl_xor_sync(0xffffffffu, x, 8);
        x += __shfl_xor_sync(0xffffffffu, x, 16);
        acc[j] = x;
    }

    __shared__ float red[8 * 8 * NACC];   // [warp][o][j]
    const int warp = tid >> 5;
    const int lane = tid & 31;
    if (lane < 8) {
#pragma unroll
        for (int j = 0; j < NACC; j++)
            red[(warp * 8 + lane) * NACC + j] = acc[j];
    }
    __syncthreads();

    // CTA totals -> compact global atomic accumulation (480 atomics/CTA)
    for (int task = tid; task < 8 * NACC; task += 256) {
        const int oo = task / NACC;
        const int j  = task - oo * NACC;
        double s = 0.0;
#pragma unroll
        for (int wp = 0; wp < 8; wp++)
            s += (double)red[(wp * 8 + oo) * NACC + j];
        atomicAdd(&g_sum[b][oo][j], (float)s);
    }

    // ---- last CTA of this b expands the 480 compact sums -> 1352 outputs ----
    __threadfence();
    if (tid == 0) {
        unsigned int t = atomicAdd(&g_ticket[b], 1u);
        s_last = (t == CPB - 1);
    }
    __syncthreads();
    if (!s_last) return;

    __shared__ float s_sum[O_][NACC];
    for (int kk = tid; kk < O_ * NACC; kk += 256) {
        const int oo = kk / NACC;
        const int j  = kk - oo * NACC;
        s_sum[oo][j] = __ldcg(&g_sum[b][oo][j]);
        g_sum[b][oo][j] = 0.0f;          // reset for next graph replay
    }
    __syncthreads();

    static const int imap[13] = {0,0,0, 1,1,1, 2,2,2, 0, 0,1,2};
    static const int kmap[13] = {0,1,2, 0,1,2, 0,1,2, 0, 3,3,3};
    static const int CIDX[3][3] = {{0,1,2},{1,3,4},{2,4,5}};
    static const int QIDX[4][4] = {{0,1,2,6},{1,3,4,7},{2,4,5,8},{6,7,8,9}};

    for (int task = tid; task < O_ * 169; task += 256) {
        const int oo = task / 169;
        const int t169 = task - oo * 169;
        const int al = t169 / 13;
        const int be = t169 - al * 13;
        float v = 0.0f;
        if (al != 9 && be != 9)
            v = s_sum[oo][CIDX[imap[al]][imap[be]] * 10 + QIDX[kmap[al]][kmap[be]]];
        out[(b * O_ + oo) * 169 + t169] = v;
    }

    if (tid == 0) g_ticket[b] = 0u;      // reset for next graph replay
}

extern "C" void kernel_launch(void* const* d_in, const int* in_sizes, int n_in,
                              void* d_out, int out_size)
{
    // Bind by size rank: w_pixel > obj > camera_matrix > coord_K.
    int order[8];
    int m = (n_in < 8) ? n_in : 8;
    for (int i = 0; i < m; i++) order[i] = i;
    for (int i = 0; i < m; i++)
        for (int j = i + 1; j < m; j++)
            if ((long long)in_sizes[order[j]] > (long long)in_sizes[order[i]]) {
                int t = order[i]; order[i] = order[j]; order[j] = t;
            }

    const void* wpix   = d_in[order[0]];
    const void* obj    = d_in[m > 1 ? order[1] : 0];
    const void* cam    = d_in[m > 2 ? order[2] : 0];
    const void* coordK = d_in[m > 3 ? order[3] : 0];
    float* out = (float*)d_out;

    mtm_onepass_kernel<<<B_ * CPB, 256>>>(obj, wpix, cam, coordK, out);
}